// round 11
// baseline (speedup 1.0000x reference)
#include <cuda_runtime.h>
#include <cuda_fp16.h>
#include <cstdint>

#define DM   1024
#define NH   16
#define HD   64
#define BSZ  4
#define TSEQ 2048
#define MROWS (BSZ * TSEQ)   // 8192

// ---------------------------------------------------------------------------
// Scratch (allocation-free rule: __device__ globals)
// ---------------------------------------------------------------------------
__device__ __align__(16) __half g_Qh[(size_t)BSZ * NH * TSEQ * HD];  // [B,H,T,hd], pre-scaled 1/8
__device__ __align__(16) __half g_Kh[(size_t)BSZ * NH * TSEQ * HD];
__device__ __align__(16) __half g_Vh[(size_t)BSZ * NH * TSEQ * HD];
__device__ __align__(16) __half g_ctxh[(size_t)MROWS * DM];          // [B,T,D] fp16
__device__ __align__(16) __half g_Af[(size_t)3 * MROWS * DM];        // fp16 acts (q,k,v)
__device__ __align__(16) __half g_Wf[(size_t)4 * DM * DM];           // fp16 W^T (q,k,v,o)

// ---------------------------------------------------------------------------
// PTX helpers (legal on plain sm_100)
// ---------------------------------------------------------------------------
__device__ __forceinline__ uint32_t smem_to_u32(const void* p) {
    uint32_t a;
    asm("{ .reg .u64 t; cvta.to.shared.u64 t, %1; cvt.u32.u64 %0, t; }"
        : "=r"(a) : "l"(p));
    return a;
}
__device__ __forceinline__ void ldmatrix_x4(uint32_t* r, uint32_t addr) {
    asm volatile("ldmatrix.sync.aligned.m8n8.x4.shared.b16 {%0,%1,%2,%3}, [%4];"
        : "=r"(r[0]), "=r"(r[1]), "=r"(r[2]), "=r"(r[3]) : "r"(addr));
}
__device__ __forceinline__ void ldmatrix_x2(uint32_t* r, uint32_t addr) {
    asm volatile("ldmatrix.sync.aligned.m8n8.x2.shared.b16 {%0,%1}, [%2];"
        : "=r"(r[0]), "=r"(r[1]) : "r"(addr));
}
__device__ __forceinline__ void mma_f16(float* d, const uint32_t* a, const uint32_t* b) {
    asm volatile(
        "mma.sync.aligned.m16n8k16.row.col.f32.f16.f16.f32 "
        "{%0,%1,%2,%3}, {%4,%5,%6,%7}, {%8,%9}, {%0,%1,%2,%3};"
        : "+f"(d[0]), "+f"(d[1]), "+f"(d[2]), "+f"(d[3])
        : "r"(a[0]), "r"(a[1]), "r"(a[2]), "r"(a[3]), "r"(b[0]), "r"(b[1]));
}
#define CP_ASYNC16(dst, src) \
    asm volatile("cp.async.cg.shared.global [%0], [%1], 16;" \
        :: "r"(dst), "l"(src) : "memory")
#define CP_COMMIT() asm volatile("cp.async.commit_group;" ::: "memory")
#define CP_WAIT(n)  asm volatile("cp.async.wait_group %0;" :: "n"(n) : "memory")

__device__ __forceinline__ uint32_t pack_h2(float lo, float hi) {
    __half2 h = __floats2half2_rn(lo, hi);
    return *reinterpret_cast<uint32_t*>(&h);
}

// ---------------------------------------------------------------------------
// Batched conversion kernels
// ---------------------------------------------------------------------------
struct ConvW4Args { const float* w[4]; };
struct ConvA3Args { const float4* x[3]; };

// 4 weights: W[K,N] fp32 -> W^T[N,K] fp16 into g_Wf slice z
__global__ void __launch_bounds__(256)
conv_w4(ConvW4Args args, __half* __restrict__ out)
{
    __shared__ float t[32][33];
    const int z = blockIdx.z;
    const float* w = args.w[z];
    __half* o = out + (size_t)z * DM * DM;
    const int k0 = blockIdx.y * 32, n0 = blockIdx.x * 32;
    const int tx = threadIdx.x, ty = threadIdx.y;   // (32, 8)
#pragma unroll
    for (int i = 0; i < 32; i += 8)
        t[ty + i][tx] = w[(size_t)(k0 + ty + i) * DM + n0 + tx];
    __syncthreads();
#pragma unroll
    for (int i = 0; i < 32; i += 8)
        o[(size_t)(n0 + ty + i) * DM + k0 + tx] = __float2half(t[tx][ty + i]);
}

// 3 activations: fp32 -> fp16 into g_Af slice z
__global__ void __launch_bounds__(256)
conv_a3(ConvA3Args args, __half* __restrict__ out, int n4)
{
    const int z = blockIdx.y;
    int i = blockIdx.x * blockDim.x + threadIdx.x;
    if (i >= n4) return;
    float4 v = args.x[z][i];
    __half2* o = reinterpret_cast<__half2*>(out + (size_t)z * MROWS * DM);
    o[2 * i]     = __floats2half2_rn(v.x, v.y);
    o[2 * i + 1] = __floats2half2_rn(v.z, v.w);
}

// ---------------------------------------------------------------------------
// HMMA GEMM core: C[M=8192, N=1024] = A[M,1024] @ W[N,1024]^T + bias
// 128x128x64 tiles, 16 k-tiles, 256 thr (2x4 warps, 64x32 warp tile),
// cp.async 2-stage, dynamic smem (73.7 KB). (R10, proven)
// ---------------------------------------------------------------------------
#define BM 128
#define BN 128
#define BK 64
#define TILE_B (BM * 72 * 2)             // 18432 bytes per operand tile
#define GSMEM  (4 * TILE_B)              // 73728
#define NKT (DM / BK)                    // 16

__device__ __forceinline__ void store2(float* p, float x, float y) {
    *reinterpret_cast<float2*>(p) = make_float2(x, y);
}
__device__ __forceinline__ void store2(__half* p, float x, float y) {
    *reinterpret_cast<__half2*>(p) = __floats2half2_rn(x, y);
}

template <typename OT, int SCATTER>
__device__ __forceinline__ void
gemm_core(const __half* __restrict__ A, const __half* __restrict__ W,
          const float* __restrict__ bias, OT* __restrict__ out, float scale,
          char* smem)
{
    const uint32_t sbase = smem_to_u32(smem);
    const int tid  = threadIdx.x;
    const int wid  = tid >> 5;
    const int lane = tid & 31;
    const int warp_m = wid >> 2;
    const int warp_n = wid & 3;
    const int m0 = blockIdx.y * BM;
    const int n0 = blockIdx.x * BN;

    float acc[4][4][4];
#pragma unroll
    for (int i = 0; i < 4; i++)
#pragma unroll
        for (int j = 0; j < 4; j++)
#pragma unroll
            for (int c = 0; c < 4; c++) acc[i][j][c] = 0.f;

    // prefetch k-tile 0 into buf 0
#pragma unroll
    for (int i = 0; i < 4; i++) {
        int lin = tid + i * 256;
        int r = lin >> 3, q = lin & 7;
        CP_ASYNC16(sbase + r * 144 + q * 16,
                   A + (size_t)(m0 + r) * DM + q * 8);
        CP_ASYNC16(sbase + TILE_B + r * 144 + q * 16,
                   W + (size_t)(n0 + r) * DM + q * 8);
    }
    CP_COMMIT();

    for (int kt = 0; kt < NKT; ++kt) {
        const int buf = kt & 1;
        if (kt + 1 < NKT) {
            const uint32_t nboff = ((kt + 1) & 1) * (2 * TILE_B);
            const int k0 = (kt + 1) * BK;
#pragma unroll
            for (int i = 0; i < 4; i++) {
                int lin = tid + i * 256;
                int r = lin >> 3, q = lin & 7;
                CP_ASYNC16(sbase + nboff + r * 144 + q * 16,
                           A + (size_t)(m0 + r) * DM + k0 + q * 8);
                CP_ASYNC16(sbase + nboff + TILE_B + r * 144 + q * 16,
                           W + (size_t)(n0 + r) * DM + k0 + q * 8);
            }
            CP_COMMIT();
            CP_WAIT(1);
        } else {
            CP_WAIT(0);
        }
        __syncthreads();

        const uint32_t sAb = sbase + buf * (2 * TILE_B);
        const uint32_t sBb = sAb + TILE_B;
#pragma unroll
        for (int kf = 0; kf < 4; ++kf) {
            uint32_t af[4][4], bf[4][2];
#pragma unroll
            for (int mf = 0; mf < 4; ++mf) {
                uint32_t addr = sAb +
                    (warp_m * 64 + mf * 16 + (lane & 15)) * 144
                    + (kf * 16 + 8 * (lane >> 4)) * 2;
                ldmatrix_x4(af[mf], addr);
            }
#pragma unroll
            for (int nf = 0; nf < 4; ++nf) {
                uint32_t addr = sBb +
                    (warp_n * 32 + nf * 8 + (lane & 7)) * 144
                    + (kf * 16 + 8 * ((lane >> 3) & 1)) * 2;
                ldmatrix_x2(bf[nf], addr);
            }
#pragma unroll
            for (int mf = 0; mf < 4; ++mf)
#pragma unroll
                for (int nf = 0; nf < 4; ++nf)
                    mma_f16(acc[mf][nf], af[mf], bf[nf]);
        }
        __syncthreads();
    }

    const int grp = lane >> 2;
    const int qd  = lane & 3;
#pragma unroll
    for (int mf = 0; mf < 4; ++mf) {
#pragma unroll
        for (int nf = 0; nf < 4; ++nf) {
            int m = m0 + warp_m * 64 + mf * 16 + grp;
            int n = n0 + warp_n * 32 + nf * 8 + qd * 2;
            float b0 = bias[n], b1 = bias[n + 1];
            float x0 = (acc[mf][nf][0] + b0) * scale;
            float y0 = (acc[mf][nf][1] + b1) * scale;
            float x1 = (acc[mf][nf][2] + b0) * scale;
            float y1 = (acc[mf][nf][3] + b1) * scale;
            if (SCATTER) {
                int bb = m >> 11, t = m & 2047;
                int hh = n >> 6,  dd = n & 63;
                size_t base = (((size_t)bb * NH + hh) * TSEQ) * HD + dd;
                store2(out + base + (size_t)t * HD, x0, y0);
                store2(out + base + (size_t)(t + 8) * HD, x1, y1);
            } else {
                store2(out + (size_t)m * DM + n, x0, y0);
                store2(out + (size_t)(m + 8) * DM + n, x1, y1);
            }
        }
    }
}

// Batched QKV GEMM: blockIdx.z selects (A, W, bias, out, scale)
struct QKVArgs {
    const float* bias[3];
    __half* out[3];
    float scale[3];
};

__global__ void __launch_bounds__(256)
gemm_qkv(const __half* __restrict__ Af, const __half* __restrict__ Wf,
         QKVArgs args)
{
    extern __shared__ char smem[];
    const int z = blockIdx.z;
    gemm_core<__half, 1>(Af + (size_t)z * MROWS * DM,
                         Wf + (size_t)z * DM * DM,
                         args.bias[z], args.out[z], args.scale[z], smem);
}

// O projection GEMM (fp32 out, row-major)
__global__ void __launch_bounds__(256)
gemm_o(const __half* __restrict__ A, const __half* __restrict__ W,
       const float* __restrict__ bias, float* __restrict__ out)
{
    extern __shared__ char smem[];
    gemm_core<float, 0>(A, W, bias, out, 1.0f, smem);
}

// ---------------------------------------------------------------------------
// HMMA causal flash attention, fp16 operands / fp32 softmax+accum (proven).
// ---------------------------------------------------------------------------
__global__ void __launch_bounds__(128)
attn_hmma(const __half* __restrict__ Q, const __half* __restrict__ K,
          const __half* __restrict__ V, __half* __restrict__ ctx)
{
    __shared__ __align__(16) __half Qs[64][72];
    __shared__ __align__(16) __half Ks[64][72];
    __shared__ __align__(16) __half Vt[64][72];   // [dim][key] (transposed at fill)

    const int qt   = gridDim.x - 1 - blockIdx.x;
    const int bh   = blockIdx.y;
    const int tid  = threadIdx.x;
    const int wid  = tid >> 5;
    const int lane = tid & 31;
    const int q0   = qt * 64;

    const __half* Qb = Q + (size_t)bh * TSEQ * HD;
    const __half* Kb = K + (size_t)bh * TSEQ * HD;
    const __half* Vb = V + (size_t)bh * TSEQ * HD;

    const uint32_t sQ = smem_to_u32(Qs);
    const uint32_t sK = smem_to_u32(Ks);
    const uint32_t sV = smem_to_u32(Vt);

#pragma unroll
    for (int it = 0; it < 4; ++it) {
        int lin = tid + it * 128;
        int r = lin >> 3, qd = lin & 7;
        *reinterpret_cast<float4*>(&Qs[r][qd * 8]) =
            *reinterpret_cast<const float4*>(&Qb[(size_t)(q0 + r) * HD + qd * 8]);
    }
    __syncthreads();

    uint32_t aq[4][4];
#pragma unroll
    for (int kc = 0; kc < 4; ++kc) {
        uint32_t addr = sQ + ((wid * 16 + (lane & 15)) * 72 + kc * 16 + 8 * (lane >> 4)) * 2;
        ldmatrix_x4(aq[kc], addr);
    }

    float o[8][4];
#pragma unroll
    for (int i = 0; i < 8; i++)
#pragma unroll
        for (int c = 0; c < 4; c++) o[i][c] = 0.f;
    float m_a = -1e30f, m_b = -1e30f, l_a = 0.f, l_b = 0.f;

    for (int kt = 0; kt <= qt; ++kt) {
        const int k0 = kt * 64;
        __syncthreads();
#pragma unroll
        for (int it = 0; it < 4; ++it) {
            int lin = tid + it * 128;
            int r = lin >> 3, qd = lin & 7;
            *reinterpret_cast<float4*>(&Ks[r][qd * 8]) =
                *reinterpret_cast<const float4*>(&Kb[(size_t)(k0 + r) * HD + qd * 8]);
        }
#pragma unroll
        for (int it = 0; it < 4; ++it) {
            int lin = tid + it * 128;
            int key = lin >> 3, qd = lin & 7;
            float4 v = *reinterpret_cast<const float4*>(&Vb[(size_t)(k0 + key) * HD + qd * 8]);
            const __half* hv = reinterpret_cast<const __half*>(&v);
#pragma unroll
            for (int i = 0; i < 8; ++i) {
                int ii = (i + qd) & 7;
                Vt[qd * 8 + ii][key] = hv[ii];
            }
        }
        __syncthreads();

        float s[8][4];
#pragma unroll
        for (int i = 0; i < 8; i++)
#pragma unroll
            for (int c = 0; c < 4; c++) s[i][c] = 0.f;
#pragma unroll
        for (int kc = 0; kc < 4; ++kc) {
#pragma unroll
            for (int j = 0; j < 4; ++j) {
                uint32_t bk[4];
                uint32_t addr = sK +
                    ((j * 16 + ((lane >> 4) << 3) + (lane & 7)) * 72
                     + kc * 16 + 8 * ((lane >> 3) & 1)) * 2;
                ldmatrix_x4(bk, addr);
                mma_f16(s[2 * j],     aq[kc], bk);
                mma_f16(s[2 * j + 1], aq[kc], bk + 2);
            }
        }

        if (kt == qt) {
            const int ra = wid * 16 + (lane >> 2);
#pragma unroll
            for (int nf = 0; nf < 8; ++nf) {
#pragma unroll
                for (int c = 0; c < 4; ++c) {
                    int key = nf * 8 + 2 * (lane & 3) + (c & 1);
                    int row = ra + 8 * (c >> 1);
                    if (key > row) s[nf][c] = -1e30f;
                }
            }
        }

        float mxa = -1e30f, mxb = -1e30f;
#pragma unroll
        for (int nf = 0; nf < 8; ++nf) {
            mxa = fmaxf(mxa, fmaxf(s[nf][0], s[nf][1]));
            mxb = fmaxf(mxb, fmaxf(s[nf][2], s[nf][3]));
        }
        mxa = fmaxf(mxa, __shfl_xor_sync(0xffffffffu, mxa, 1));
        mxa = fmaxf(mxa, __shfl_xor_sync(0xffffffffu, mxa, 2));
        mxb = fmaxf(mxb, __shfl_xor_sync(0xffffffffu, mxb, 1));
        mxb = fmaxf(mxb, __shfl_xor_sync(0xffffffffu, mxb, 2));
        float mna = fmaxf(m_a, mxa), mnb = fmaxf(m_b, mxb);
        float ala = __expf(m_a - mna), alb = __expf(m_b - mnb);
        float sa = 0.f, sb = 0.f;
#pragma unroll
        for (int nf = 0; nf < 8; ++nf) {
            s[nf][0] = __expf(s[nf][0] - mna);
            s[nf][1] = __expf(s[nf][1] - mna);
            s[nf][2] = __expf(s[nf][2] - mnb);
            s[nf][3] = __expf(s[nf][3] - mnb);
            sa += s[nf][0] + s[nf][1];
            sb += s[nf][2] + s[nf][3];
        }
        sa += __shfl_xor_sync(0xffffffffu, sa, 1);
        sa += __shfl_xor_sync(0xffffffffu, sa, 2);
        sb += __shfl_xor_sync(0xffffffffu, sb, 1);
        sb += __shfl_xor_sync(0xffffffffu, sb, 2);
        l_a = l_a * ala + sa;  m_a = mna;
        l_b = l_b * alb + sb;  m_b = mnb;
#pragma unroll
        for (int nf = 0; nf < 8; ++nf) {
            o[nf][0] *= ala; o[nf][1] *= ala;
            o[nf][2] *= alb; o[nf][3] *= alb;
        }

#pragma unroll
        for (int kc2 = 0; kc2 < 4; ++kc2) {
            uint32_t ap[4];
            ap[0] = pack_h2(s[2 * kc2][0],     s[2 * kc2][1]);
            ap[1] = pack_h2(s[2 * kc2][2],     s[2 * kc2][3]);
            ap[2] = pack_h2(s[2 * kc2 + 1][0], s[2 * kc2 + 1][1]);
            ap[3] = pack_h2(s[2 * kc2 + 1][2], s[2 * kc2 + 1][3]);
#pragma unroll
            for (int nf2 = 0; nf2 < 4; ++nf2) {
                uint32_t bv[4];
                uint32_t addr = sV +
                    ((nf2 * 16 + ((lane >> 4) << 3) + (lane & 7)) * 72
                     + kc2 * 16 + 8 * ((lane >> 3) & 1)) * 2;
                ldmatrix_x4(bv, addr);
                mma_f16(o[2 * nf2],     ap, bv);
                mma_f16(o[2 * nf2 + 1], ap, bv + 2);
            }
        }
    }

    const int b = bh >> 4;
    const int h = bh & 15;
    const int ta = q0 + wid * 16 + (lane >> 2);
    const int tb = ta + 8;
    const float inva = 1.0f / l_a;
    const float invb = 1.0f / l_b;
#pragma unroll
    for (int nf = 0; nf < 8; ++nf) {
        int col = h * HD + nf * 8 + 2 * (lane & 3);
        *reinterpret_cast<__half2*>(&ctx[(size_t)(b * TSEQ + ta) * DM + col]) =
            __floats2half2_rn(o[nf][0] * inva, o[nf][1] * inva);
        *reinterpret_cast<__half2*>(&ctx[(size_t)(b * TSEQ + tb) * DM + col]) =
            __floats2half2_rn(o[nf][2] * invb, o[nf][3] * invb);
    }
}

// ---------------------------------------------------------------------------
extern "C" void kernel_launch(void* const* d_in, const int* in_sizes, int n_in,
                              void* d_out, int out_size)
{
    const float* q  = (const float*)d_in[0];
    const float* k  = (const float*)d_in[1];
    const float* v  = (const float*)d_in[2];
    const float* wq = (const float*)d_in[3];
    const float* bq = (const float*)d_in[4];
    const float* wk = (const float*)d_in[5];
    const float* bk = (const float*)d_in[6];
    const float* wv = (const float*)d_in[7];
    const float* bv = (const float*)d_in[8];
    const float* wo = (const float*)d_in[9];
    const float* bo = (const float*)d_in[10];

    __half *Qp, *Kp, *Vp, *Cp, *Afp, *Wfp;
    cudaGetSymbolAddress((void**)&Qp,  g_Qh);
    cudaGetSymbolAddress((void**)&Kp,  g_Kh);
    cudaGetSymbolAddress((void**)&Vp,  g_Vh);
    cudaGetSymbolAddress((void**)&Cp,  g_ctxh);
    cudaGetSymbolAddress((void**)&Afp, g_Af);
    cudaGetSymbolAddress((void**)&Wfp, g_Wf);

    cudaFuncSetAttribute(gemm_qkv, cudaFuncAttributeMaxDynamicSharedMemorySize, GSMEM);
    cudaFuncSetAttribute(gemm_o,   cudaFuncAttributeMaxDynamicSharedMemorySize, GSMEM);

    // 1) all 4 weight transposes+converts in one launch
    ConvW4Args wargs;
    wargs.w[0] = wq; wargs.w[1] = wk; wargs.w[2] = wv; wargs.w[3] = wo;
    conv_w4<<<dim3(DM / 32, DM / 32, 4), dim3(32, 8)>>>(wargs, Wfp);

    // 2) q,k,v activation converts in one launch
    const int n4 = MROWS * DM / 4;
    ConvA3Args aargs;
    aargs.x[0] = (const float4*)q;
    aargs.x[1] = (const float4*)k;
    aargs.x[2] = (const float4*)v;
    conv_a3<<<dim3((n4 + 255) / 256, 3), dim3(256)>>>(aargs, Afp, n4);

    // 3) batched QKV projections (Q pre-scaled by 1/sqrt(hd) = 0.125)
    QKVArgs gargs;
    gargs.bias[0] = bq; gargs.bias[1] = bk; gargs.bias[2] = bv;
    gargs.out[0]  = Qp; gargs.out[1]  = Kp; gargs.out[2]  = Vp;
    gargs.scale[0] = 0.125f; gargs.scale[1] = 1.0f; gargs.scale[2] = 1.0f;
    gemm_qkv<<<dim3(DM / BN, MROWS / BM, 3), dim3(256), GSMEM>>>(Afp, Wfp, gargs);

    // 4) attention (HMMA fp16, writes fp16 ctx)
    attn_hmma<<<dim3(TSEQ / 64, BSZ * NH), dim3(128)>>>(Qp, Kp, Vp, Cp);

    // 5) output projection (fp32 out)
    gemm_o<<<dim3(DM / BN, MROWS / BM), dim3(256), GSMEM>>>(
        Cp, Wfp + (size_t)3 * DM * DM, bo, (float*)d_out);
}